// round 4
// baseline (speedup 1.0000x reference)
#include <cuda_runtime.h>

#define B 128
#define K 17
#define HW 9216          // 96*96
#define NVEC (HW/4)      // 2304
#define TOPK 8
#define THREADS1 256
#define NBLOCKS (B * K)  // 2176

__device__ float g_per_joint[B * K];
__device__ unsigned int g_counter = 0;

__global__ void __launch_bounds__(THREADS1, 4)
mse_ohkm_fused_kernel(const float* __restrict__ pred,
                      const float* __restrict__ gt,
                      const float* __restrict__ tw,
                      float* __restrict__ out) {
    const int bk = blockIdx.x;
    const int tid = threadIdx.x;
    const float4* __restrict__ p = reinterpret_cast<const float4*>(pred + (size_t)bk * HW);
    const float4* __restrict__ g = reinterpret_cast<const float4*>(gt   + (size_t)bk * HW);
    const float w = tw[bk];

    float acc = 0.0f;
    #pragma unroll
    for (int j = 0; j < NVEC / THREADS1; j++) {   // 9 iterations
        const int i = tid + j * THREADS1;
        float4 a = p[i];
        float4 b = g[i];
        float d0 = (a.x - b.x) * w;
        float d1 = (a.y - b.y) * w;
        float d2 = (a.z - b.z) * w;
        float d3 = (a.w - b.w) * w;
        acc += d0 * d0 + d1 * d1 + d2 * d2 + d3 * d3;
    }

    // block reduce
    #pragma unroll
    for (int off = 16; off > 0; off >>= 1)
        acc += __shfl_down_sync(0xFFFFFFFFu, acc, off);

    __shared__ float warp_sums[THREADS1 / 32];
    __shared__ unsigned int is_last;
    const int lane = tid & 31;
    const int wid  = tid >> 5;
    if (lane == 0) warp_sums[wid] = acc;
    __syncthreads();

    if (wid == 0) {
        float v = (lane < THREADS1 / 32) ? warp_sums[lane] : 0.0f;
        #pragma unroll
        for (int off = 4; off > 0; off >>= 1)
            v += __shfl_down_sync(0xFFFFFFFFu, v, off);
        if (lane == 0) {
            g_per_joint[bk] = v * (1.0f / (float)HW);
            // release-atomic: orders the store above without a full
            // gpu-scope threadfence (no CCTL.IVALL in every block)
            unsigned int old;
            asm volatile("atom.add.release.gpu.global.u32 %0, [%1], 1;"
                         : "=r"(old) : "l"(&g_counter) : "memory");
            is_last = (old == (unsigned int)(NBLOCKS - 1)) ? 1u : 0u;
        }
    }
    __syncthreads();
    if (!is_last) return;

    // ---- last block only: OHKM top-k over the L2-hot per-joint array ----
    asm volatile("fence.acq_rel.gpu;" ::: "memory");

    __shared__ float sh[B];
    if (tid < B) {
        float t[TOPK];
        #pragma unroll
        for (int j = 0; j < TOPK; j++) t[j] = -3.4e38f;

        #pragma unroll
        for (int i = 0; i < K; i++) {
            float x = __ldcg(&g_per_joint[tid * K + i]);   // bypass L1
            #pragma unroll
            for (int j = 0; j < TOPK; j++) {
                float old = t[j];
                bool gtp = x > old;
                t[j] = gtp ? x : old;
                x    = gtp ? old : x;
            }
        }
        float s = 0.0f;
        #pragma unroll
        for (int j = 0; j < TOPK; j++) s += t[j];
        sh[tid] = s;
    }
    __syncthreads();

    #pragma unroll
    for (int stride = B / 2; stride > 0; stride >>= 1) {
        if (tid < stride) sh[tid] += sh[tid + stride];
        __syncthreads();
    }
    if (tid == 0) {
        out[0] = sh[0] * (1.0f / (float)(B * TOPK));
        g_counter = 0u;   // reset for next graph replay
    }
}

extern "C" void kernel_launch(void* const* d_in, const int* in_sizes, int n_in,
                              void* d_out, int out_size) {
    const float* pred = (const float*)d_in[0];   // output [B,K,H,W]
    const float* gt   = (const float*)d_in[1];   // target [B,K,H,W]
    const float* tw   = (const float*)d_in[2];   // target_weight [B,K,1]
    float* out = (float*)d_out;

    mse_ohkm_fused_kernel<<<NBLOCKS, THREADS1>>>(pred, gt, tw, out);
}

// round 5
// speedup vs baseline: 1.0010x; 1.0010x over previous
#include <cuda_runtime.h>

#define B 128
#define K 17
#define HW 9216          // 96*96
#define NVEC (HW/4)      // 2304
#define TOPK 8
#define THREADS1 256

__device__ float g_per_joint[B * K];

__global__ void __launch_bounds__(THREADS1, 4)
mse_per_joint_kernel(const float* __restrict__ pred,
                     const float* __restrict__ gt,
                     const float* __restrict__ tw) {
    const int bk = blockIdx.x;                    // 0 .. B*K-1
    const float4* __restrict__ p = reinterpret_cast<const float4*>(pred + (size_t)bk * HW);
    const float4* __restrict__ g = reinterpret_cast<const float4*>(gt   + (size_t)bk * HW);

    float acc = 0.0f;
    #pragma unroll
    for (int j = 0; j < NVEC / THREADS1; j++) {   // 9 iterations, fully unrolled
        const int i = threadIdx.x + j * THREADS1;
        float4 a = p[i];
        float4 b = g[i];
        float d0 = a.x - b.x;
        float d1 = a.y - b.y;
        float d2 = a.z - b.z;
        float d3 = a.w - b.w;
        acc += d0 * d0 + d1 * d1 + d2 * d2 + d3 * d3;
    }

    // warp reduce
    #pragma unroll
    for (int off = 16; off > 0; off >>= 1)
        acc += __shfl_down_sync(0xFFFFFFFFu, acc, off);

    __shared__ float warp_sums[THREADS1 / 32];
    const int lane = threadIdx.x & 31;
    const int wid  = threadIdx.x >> 5;
    if (lane == 0) warp_sums[wid] = acc;
    __syncthreads();

    if (wid == 0) {
        float v = (lane < THREADS1 / 32) ? warp_sums[lane] : 0.0f;
        #pragma unroll
        for (int off = 4; off > 0; off >>= 1)
            v += __shfl_down_sync(0xFFFFFFFFu, v, off);
        if (lane == 0) {
            const float w = tw[bk];                // weight applied once, squared
            g_per_joint[bk] = v * w * w * (1.0f / (float)HW);
        }
    }
}

__global__ void __launch_bounds__(B, 1)
ohkm_topk_kernel(float* __restrict__ out) {
    // PDL: this kernel is resident on-chip before the primary finishes;
    // wait here until the primary's memory writes are visible.
#if __CUDA_ARCH__ >= 900
    cudaGridDependencySynchronize();
#endif
    const int b = threadIdx.x;   // one thread per sample

    // Register-resident top-8 insertion network (sorted descending, static idx).
    float t[TOPK];
    #pragma unroll
    for (int j = 0; j < TOPK; j++) t[j] = -3.4e38f;

    #pragma unroll
    for (int i = 0; i < K; i++) {
        float x = g_per_joint[b * K + i];
        #pragma unroll
        for (int j = 0; j < TOPK; j++) {
            float old = t[j];
            bool gtp = x > old;
            t[j] = gtp ? x : old;
            x    = gtp ? old : x;
        }
    }

    float s = 0.0f;
    #pragma unroll
    for (int j = 0; j < TOPK; j++) s += t[j];

    __shared__ float sh[B];
    sh[b] = s;
    __syncthreads();
    #pragma unroll
    for (int stride = B / 2; stride > 0; stride >>= 1) {
        if (b < stride) sh[b] += sh[b + stride];
        __syncthreads();
    }
    if (b == 0)
        out[0] = sh[0] * (1.0f / (float)(B * TOPK));
}

extern "C" void kernel_launch(void* const* d_in, const int* in_sizes, int n_in,
                              void* d_out, int out_size) {
    const float* pred = (const float*)d_in[0];   // output [B,K,H,W]
    const float* gt   = (const float*)d_in[1];   // target [B,K,H,W]
    const float* tw   = (const float*)d_in[2];   // target_weight [B,K,1]
    float* out = (float*)d_out;

    mse_per_joint_kernel<<<B * K, THREADS1>>>(pred, gt, tw);

    // Secondary launch with Programmatic Dependent Launch: overlap its
    // launch/setup with the primary's drain.
    cudaLaunchConfig_t cfg = {};
    cfg.gridDim = dim3(1, 1, 1);
    cfg.blockDim = dim3(B, 1, 1);
    cfg.dynamicSmemBytes = 0;
    cfg.stream = 0;
    cudaLaunchAttribute attr[1];
    attr[0].id = cudaLaunchAttributeProgrammaticStreamSerialization;
    attr[0].val.programmaticStreamSerializationAllowed = 1;
    cfg.attrs = attr;
    cfg.numAttrs = 1;
    cudaError_t e = cudaLaunchKernelEx(&cfg, ohkm_topk_kernel, out);
    if (e != cudaSuccess) {
        // Fallback: plain launch (still correct, just not overlapped)
        ohkm_topk_kernel<<<1, B>>>(out);
    }
}

// round 6
// speedup vs baseline: 1.0165x; 1.0155x over previous
#include <cuda_runtime.h>

#define B 128
#define K 17
#define HW 9216          // 96*96
#define NVEC (HW/4)      // 2304
#define TOPK 8
#define THREADS1 256
#define NTILES (B * K)   // 2176
#define GRIDX 592        // 148 SMs * 4 resident blocks -> single wave

__device__ float g_per_joint[B * K];
__device__ unsigned int g_counter = 0;

__global__ void __launch_bounds__(THREADS1, 4)
mse_ohkm_persistent_kernel(const float* __restrict__ pred,
                           const float* __restrict__ gt,
                           const float* __restrict__ tw,
                           float* __restrict__ out) {
    const int tid  = threadIdx.x;
    const int lane = tid & 31;
    const int wid  = tid >> 5;
    __shared__ float warp_sums[THREADS1 / 32];
    __shared__ unsigned int is_last;

    // ---- persistent loop: each block handles tiles bk, bk+592, ... ----
    for (int bk = blockIdx.x; bk < NTILES; bk += GRIDX) {
        const float4* __restrict__ p = reinterpret_cast<const float4*>(pred + (size_t)bk * HW);
        const float4* __restrict__ g = reinterpret_cast<const float4*>(gt   + (size_t)bk * HW);

        float acc = 0.0f;
        #pragma unroll
        for (int j = 0; j < NVEC / THREADS1; j++) {   // 9 iterations
            const int i = tid + j * THREADS1;
            float4 a = p[i];
            float4 b = g[i];
            float d0 = a.x - b.x;
            float d1 = a.y - b.y;
            float d2 = a.z - b.z;
            float d3 = a.w - b.w;
            acc += d0 * d0 + d1 * d1 + d2 * d2 + d3 * d3;
        }

        #pragma unroll
        for (int off = 16; off > 0; off >>= 1)
            acc += __shfl_down_sync(0xFFFFFFFFu, acc, off);

        if (lane == 0) warp_sums[wid] = acc;
        __syncthreads();

        if (wid == 0) {
            float v = (lane < THREADS1 / 32) ? warp_sums[lane] : 0.0f;
            #pragma unroll
            for (int off = 4; off > 0; off >>= 1)
                v += __shfl_down_sync(0xFFFFFFFFu, v, off);
            if (lane == 0) {
                const float w = tw[bk];
                g_per_joint[bk] = v * w * w * (1.0f / (float)HW);
            }
        }
        __syncthreads();   // warp_sums reused next iteration
    }

    // ---- one release-atomic per BLOCK (592 total, not 2176) ----
    if (tid == 0) {
        unsigned int old;
        asm volatile("atom.add.release.gpu.global.u32 %0, [%1], 1;"
                     : "=r"(old) : "l"(&g_counter) : "memory");
        is_last = (old == (unsigned int)(GRIDX - 1)) ? 1u : 0u;
    }
    __syncthreads();
    if (!is_last) return;

    // ---- last block: OHKM top-k over L2-hot per-joint values ----
    asm volatile("fence.acq_rel.gpu;" ::: "memory");

    __shared__ float sh[B];
    if (tid < B) {
        float t[TOPK];
        #pragma unroll
        for (int j = 0; j < TOPK; j++) t[j] = -3.4e38f;

        #pragma unroll
        for (int i = 0; i < K; i++) {
            float x = __ldcg(&g_per_joint[tid * K + i]);
            #pragma unroll
            for (int j = 0; j < TOPK; j++) {
                float old = t[j];
                bool gtp = x > old;
                t[j] = gtp ? x : old;
                x    = gtp ? old : x;
            }
        }
        float s = 0.0f;
        #pragma unroll
        for (int j = 0; j < TOPK; j++) s += t[j];
        sh[tid] = s;
    }
    __syncthreads();

    #pragma unroll
    for (int stride = B / 2; stride > 0; stride >>= 1) {
        if (tid < stride) sh[tid] += sh[tid + stride];
        __syncthreads();
    }
    if (tid == 0) {
        out[0] = sh[0] * (1.0f / (float)(B * TOPK));
        g_counter = 0u;   // reset for next graph replay
    }
}

extern "C" void kernel_launch(void* const* d_in, const int* in_sizes, int n_in,
                              void* d_out, int out_size) {
    const float* pred = (const float*)d_in[0];   // output [B,K,H,W]
    const float* gt   = (const float*)d_in[1];   // target [B,K,H,W]
    const float* tw   = (const float*)d_in[2];   // target_weight [B,K,1]
    float* out = (float*)d_out;

    mse_ohkm_persistent_kernel<<<GRIDX, THREADS1>>>(pred, gt, tw, out);
}